// round 4
// baseline (speedup 1.0000x reference)
#include <cuda_runtime.h>
#include <cstdint>
#include <cstddef>

// Problem shape (fixed for this problem instance)
#define NROW 8192
#define DIN  256
#define DOUT 256

// -------- device scratch (no allocations allowed) --------
__device__ float g_d[NROW];            // d_i = (1 + deg_i)^-1/2
__device__ float g_h[(size_t)NROW * DOUT]; // h' = diag(d) * (x @ W^T), fp32

// -------- helpers --------
__device__ __forceinline__ uint32_t f2tf(float f) {
    uint32_t r;
    asm("cvt.rna.tf32.f32 %0, %1;" : "=r"(r) : "f"(f));
    return r;
}

__device__ __forceinline__ void mma_tf32(float (&c)[4],
                                         uint32_t a0, uint32_t a1, uint32_t a2, uint32_t a3,
                                         uint32_t b0, uint32_t b1) {
    asm volatile(
        "mma.sync.aligned.m16n8k8.row.col.f32.tf32.tf32.f32 "
        "{%0,%1,%2,%3}, {%4,%5,%6,%7}, {%8,%9}, {%0,%1,%2,%3};"
        : "+f"(c[0]), "+f"(c[1]), "+f"(c[2]), "+f"(c[3])
        : "r"(a0), "r"(a1), "r"(a2), "r"(a3), "r"(b0), "r"(b1));
}

// ============================================================
// Kernel 1: fused degree + A copy.
// One block per row. Reads A row once, writes copy to output region,
// computes d[i] = rsqrt(1 + sum(A[i,j] - 1e-15 > 0)).
// ============================================================
__global__ __launch_bounds__(256) void k_deg_copy(const float* __restrict__ A,
                                                  float* __restrict__ a_out,
                                                  int do_copy) {
    const int row = blockIdx.x;
    const float4* __restrict__ Ar = reinterpret_cast<const float4*>(A + (size_t)row * NROW);
    float4* __restrict__ Or = reinterpret_cast<float4*>(a_out + (size_t)row * NROW);

    float cnt = 0.f;
#pragma unroll 4
    for (int c = threadIdx.x; c < NROW / 4; c += 256) {
        float4 v = Ar[c];
        if (do_copy) Or[c] = v;
        cnt += (v.x - 1e-15f > 0.f) ? 1.f : 0.f;
        cnt += (v.y - 1e-15f > 0.f) ? 1.f : 0.f;
        cnt += (v.z - 1e-15f > 0.f) ? 1.f : 0.f;
        cnt += (v.w - 1e-15f > 0.f) ? 1.f : 0.f;
    }
#pragma unroll
    for (int o = 16; o; o >>= 1) cnt += __shfl_down_sync(0xffffffffu, cnt, o);

    __shared__ float wsum[8];
    const int warp = threadIdx.x >> 5, lane = threadIdx.x & 31;
    if (lane == 0) wsum[warp] = cnt;
    __syncthreads();
    if (threadIdx.x == 0) {
        float s = 1.f;
#pragma unroll
        for (int i = 0; i < 8; i++) s += wsum[i];
        float r = rsqrtf(s);
        r = r * (1.5f - 0.5f * s * r * r);   // Newton refine for fp32 accuracy
        g_d[row] = r;
    }
}

// ============================================================
// Kernel 2: h' = diag(d) * (x @ W^T), fp32.
// Block computes 64x64 tile; transposed smem tiles for conflict-free
// float4 inner loads. grid = (DOUT/64, NROW/64).
// ============================================================
__global__ __launch_bounds__(256) void k_h(const float* __restrict__ x,
                                           const float* __restrict__ W) {
    constexpr int STR = 68;  // 64 + 4 pad, float4-aligned
    __shared__ float xs_t[32][STR];  // [k][i]
    __shared__ float ws_t[32][STR];  // [k][j]

    const int tid = threadIdx.x;
    const int tx = tid & 15, ty = tid >> 4;
    const int row0 = blockIdx.y * 64;
    const int col0 = blockIdx.x * 64;

    float acc[4][4];
#pragma unroll
    for (int m = 0; m < 4; m++)
#pragma unroll
        for (int n = 0; n < 4; n++) acc[m][n] = 0.f;

    for (int t = 0; t < DIN / 32; ++t) {
        // load 64x32 tiles (2 float4 per thread each), store transposed
#pragma unroll
        for (int i = 0; i < 2; i++) {
            const int f4 = tid + i * 256;
            const int r = f4 >> 3;          // 0..63
            const int kc = (f4 & 7) * 4;    // 0..28
            float4 xv = *reinterpret_cast<const float4*>(x + (size_t)(row0 + r) * DIN + t * 32 + kc);
            float4 wv = *reinterpret_cast<const float4*>(W + (size_t)(col0 + r) * DIN + t * 32 + kc);
            xs_t[kc + 0][r] = xv.x; xs_t[kc + 1][r] = xv.y;
            xs_t[kc + 2][r] = xv.z; xs_t[kc + 3][r] = xv.w;
            ws_t[kc + 0][r] = wv.x; ws_t[kc + 1][r] = wv.y;
            ws_t[kc + 2][r] = wv.z; ws_t[kc + 3][r] = wv.w;
        }
        __syncthreads();
#pragma unroll
        for (int k = 0; k < 32; k++) {
            float4 xv = *reinterpret_cast<const float4*>(&xs_t[k][ty * 4]);
            float4 wv = *reinterpret_cast<const float4*>(&ws_t[k][tx * 4]);
            const float xr[4] = {xv.x, xv.y, xv.z, xv.w};
            const float wr[4] = {wv.x, wv.y, wv.z, wv.w};
#pragma unroll
            for (int m = 0; m < 4; m++)
#pragma unroll
                for (int n = 0; n < 4; n++) acc[m][n] += xr[m] * wr[n];
        }
        __syncthreads();
    }

#pragma unroll
    for (int m = 0; m < 4; m++) {
        const int i = row0 + ty * 4 + m;
        const float di = g_d[i];
#pragma unroll
        for (int n = 0; n < 4; n++) {
            g_h[(size_t)i * DOUT + col0 + tx * 4 + n] = di * acc[m][n];
        }
    }
}

// ============================================================
// Kernel 3: out = relu(diag(d) * (A @ h' + h')), tf32 mma.sync.
// BM=128 BN=128 BK=16, 256 threads = 8 warps as 4(m) x 2(n),
// warp tile 32x64 => 2 m-tiles x 8 n-tiles of m16n8k8.
// Double-buffered smem, register-staged LDG -> cvt.rna.tf32 -> STS.
// ============================================================
constexpr int BM = 128, BN = 128, BK = 16;
constexpr int ASTR = 20;   // BK+4: frag LDS banks (20*g+tg)%32 all distinct
constexpr int BSTR = 136;  // BN+8: frag LDS banks (8*tg+g)%32 all distinct
constexpr int NT_ITERS = NROW / BK;  // 512

__global__ __launch_bounds__(256) void k_main(const float* __restrict__ A,
                                              float* __restrict__ out) {
    __shared__ uint32_t As[2][BM * ASTR];
    __shared__ uint32_t Bs[2][BK * BSTR];

    const int tid = threadIdx.x;
    const int warp = tid >> 5, lane = tid & 31;
    const int wm = warp >> 1, wn = warp & 1;
    const int g = lane >> 2, tg = lane & 3;

    const int row0 = blockIdx.y * BM;
    const int col0 = blockIdx.x * BN;

    // A loader: 128x16 floats = 512 float4; 2 per thread
    const int ar0 = tid >> 2;               // 0..63
    const int ar1 = ar0 + 64;               // 64..127
    const int ak = (tid & 3) * 4;           // 0,4,8,12
    // B loader: 16x128 floats = 512 float4; 2 per thread
    const int br0 = tid >> 5;               // 0..7
    const int br1 = br0 + 8;                // 8..15
    const int bn = (tid & 31) * 4;          // 0..124

    const float* __restrict__ Ap0 = A + (size_t)(row0 + ar0) * NROW + ak;
    const float* __restrict__ Ap1 = A + (size_t)(row0 + ar1) * NROW + ak;
    const float* __restrict__ Bp0 = g_h + (size_t)br0 * DOUT + col0 + bn;
    const float* __restrict__ Bp1 = g_h + (size_t)br1 * DOUT + col0 + bn;

    float acc[2][8][4];
#pragma unroll
    for (int mt = 0; mt < 2; mt++)
#pragma unroll
        for (int nt = 0; nt < 8; nt++)
#pragma unroll
            for (int i = 0; i < 4; i++) acc[mt][nt][i] = 0.f;

    // --- prologue: stage tile 0 ---
    {
        float4 a0 = *reinterpret_cast<const float4*>(Ap0);
        float4 a1 = *reinterpret_cast<const float4*>(Ap1);
        float4 b0 = *reinterpret_cast<const float4*>(Bp0);
        float4 b1 = *reinterpret_cast<const float4*>(Bp1);
        uint4 u;
        u.x = f2tf(a0.x); u.y = f2tf(a0.y); u.z = f2tf(a0.z); u.w = f2tf(a0.w);
        *reinterpret_cast<uint4*>(&As[0][ar0 * ASTR + ak]) = u;
        u.x = f2tf(a1.x); u.y = f2tf(a1.y); u.z = f2tf(a1.z); u.w = f2tf(a1.w);
        *reinterpret_cast<uint4*>(&As[0][ar1 * ASTR + ak]) = u;
        u.x = f2tf(b0.x); u.y = f2tf(b0.y); u.z = f2tf(b0.z); u.w = f2tf(b0.w);
        *reinterpret_cast<uint4*>(&Bs[0][br0 * BSTR + bn]) = u;
        u.x = f2tf(b1.x); u.y = f2tf(b1.y); u.z = f2tf(b1.z); u.w = f2tf(b1.w);
        *reinterpret_cast<uint4*>(&Bs[0][br1 * BSTR + bn]) = u;
    }
    __syncthreads();

#pragma unroll 2
    for (int t = 0; t < NT_ITERS; ++t) {
        const int s = t & 1;
        float4 na0, na1, nb0, nb1;
        const bool more = (t + 1 < NT_ITERS);
        if (more) {
            na0 = *reinterpret_cast<const float4*>(Ap0 + (size_t)(t + 1) * BK);
            na1 = *reinterpret_cast<const float4*>(Ap1 + (size_t)(t + 1) * BK);
            nb0 = *reinterpret_cast<const float4*>(Bp0 + (size_t)(t + 1) * BK * DOUT);
            nb1 = *reinterpret_cast<const float4*>(Bp1 + (size_t)(t + 1) * BK * DOUT);
        }

        const uint32_t* __restrict__ as = As[s];
        const uint32_t* __restrict__ bs = Bs[s];
#pragma unroll
        for (int ks = 0; ks < 2; ++ks) {
            uint32_t af[2][4];
            const int kk = ks * 8 + tg;
#pragma unroll
            for (int mt = 0; mt < 2; ++mt) {
                const int r = wm * 32 + mt * 16 + g;
                af[mt][0] = as[(r)     * ASTR + kk];
                af[mt][1] = as[(r + 8) * ASTR + kk];
                af[mt][2] = as[(r)     * ASTR + kk + 4];
                af[mt][3] = as[(r + 8) * ASTR + kk + 4];
            }
#pragma unroll
            for (int nt = 0; nt < 8; ++nt) {
                const int c = wn * 64 + nt * 8 + g;
                const uint32_t bf0 = bs[(ks * 8 + tg)     * BSTR + c];
                const uint32_t bf1 = bs[(ks * 8 + tg + 4) * BSTR + c];
                mma_tf32(acc[0][nt], af[0][0], af[0][1], af[0][2], af[0][3], bf0, bf1);
                mma_tf32(acc[1][nt], af[1][0], af[1][1], af[1][2], af[1][3], bf0, bf1);
            }
        }

        if (more) {
            const int s2 = s ^ 1;
            uint4 u;
            u.x = f2tf(na0.x); u.y = f2tf(na0.y); u.z = f2tf(na0.z); u.w = f2tf(na0.w);
            *reinterpret_cast<uint4*>(&As[s2][ar0 * ASTR + ak]) = u;
            u.x = f2tf(na1.x); u.y = f2tf(na1.y); u.z = f2tf(na1.z); u.w = f2tf(na1.w);
            *reinterpret_cast<uint4*>(&As[s2][ar1 * ASTR + ak]) = u;
            u.x = f2tf(nb0.x); u.y = f2tf(nb0.y); u.z = f2tf(nb0.z); u.w = f2tf(nb0.w);
            *reinterpret_cast<uint4*>(&Bs[s2][br0 * BSTR + bn]) = u;
            u.x = f2tf(nb1.x); u.y = f2tf(nb1.y); u.z = f2tf(nb1.z); u.w = f2tf(nb1.w);
            *reinterpret_cast<uint4*>(&Bs[s2][br1 * BSTR + bn]) = u;
        }
        __syncthreads();
    }

    // --- epilogue: out = relu(d_i * (acc + h'_i)) ---
#pragma unroll
    for (int mt = 0; mt < 2; ++mt) {
        const int r_lo = row0 + wm * 32 + mt * 16 + g;
        const int r_hi = r_lo + 8;
        const float dlo = g_d[r_lo];
        const float dhi = g_d[r_hi];
#pragma unroll
        for (int nt = 0; nt < 8; ++nt) {
            const int c = col0 + wn * 64 + nt * 8 + 2 * tg;
            const float h00 = g_h[(size_t)r_lo * DOUT + c];
            const float h01 = g_h[(size_t)r_lo * DOUT + c + 1];
            const float h10 = g_h[(size_t)r_hi * DOUT + c];
            const float h11 = g_h[(size_t)r_hi * DOUT + c + 1];
            float2 vlo, vhi;
            vlo.x = fmaxf(dlo * (acc[mt][nt][0] + h00), 0.f);
            vlo.y = fmaxf(dlo * (acc[mt][nt][1] + h01), 0.f);
            vhi.x = fmaxf(dhi * (acc[mt][nt][2] + h10), 0.f);
            vhi.y = fmaxf(dhi * (acc[mt][nt][3] + h11), 0.f);
            *reinterpret_cast<float2*>(out + (size_t)r_lo * DOUT + c) = vlo;
            *reinterpret_cast<float2*>(out + (size_t)r_hi * DOUT + c) = vhi;
        }
    }
}

// ============================================================
// Launch
// ============================================================
extern "C" void kernel_launch(void* const* d_in, const int* in_sizes, int n_in,
                              void* d_out, int out_size) {
    const float* x = (const float*)d_in[0];  // [NROW, DIN]
    const float* A = (const float*)d_in[1];  // [NROW, NROW]
    const float* W = (const float*)d_in[2];  // [DOUT, DIN]
    float* out = (float*)d_out;

    const long long out_elems = (long long)NROW * DOUT;
    const long long a_elems = (long long)NROW * NROW;
    const int do_copy = ((long long)out_size >= out_elems + a_elems) ? 1 : 0;
    float* a_copy = out + out_elems;  // tuple output: (out, A)

    // 1) degree + d + A copy (fused single pass over A)
    k_deg_copy<<<NROW, 256>>>(A, do_copy ? a_copy : out, do_copy);

    // 2) h' = diag(d) * (x @ W^T)
    k_h<<<dim3(DOUT / 64, NROW / 64), 256>>>(x, W);

    // 3) out = relu(diag(d) * (A @ h' + h'))
    k_main<<<dim3(BN == 128 ? DOUT / BN : 2, NROW / BM), 256>>>(A, out);
}

// round 6
// speedup vs baseline: 1.3105x; 1.3105x over previous
#include <cuda_runtime.h>
#include <cstdint>
#include <cstddef>

#define NROW 8192
#define DIN  256
#define DOUT 256

// -------- device scratch (no allocations allowed) --------
__device__ float g_d[NROW];                      // d_i = (1 + deg_i)^-1/2
__device__ float g_At[(size_t)NROW * NROW];      // tf32(rna)-rounded A, 256 MB
__device__ float g_ht[(size_t)DOUT * NROW];      // tf32-rounded h'^T: g_ht[j][i] = d_i*(x@W^T)[i][j]

// -------- helpers --------
__device__ __forceinline__ uint32_t f2tf(float f) {
    uint32_t r; asm("cvt.rna.tf32.f32 %0, %1;" : "=r"(r) : "f"(f)); return r;
}
__device__ __forceinline__ uint32_t smem_u32(const void* p) {
    uint32_t a;
    asm("{ .reg .u64 t; cvta.to.shared.u64 t, %1; cvt.u32.u64 %0, t; }" : "=r"(a) : "l"(p));
    return a;
}
#define SWZ(off) ((off) ^ (((off) >> 3) & 0x70))

__device__ __forceinline__ void mma_tf32(float (&c)[4],
                                         uint32_t a0, uint32_t a1, uint32_t a2, uint32_t a3,
                                         uint32_t b0, uint32_t b1) {
    asm volatile(
        "mma.sync.aligned.m16n8k8.row.col.f32.tf32.tf32.f32 "
        "{%0,%1,%2,%3}, {%4,%5,%6,%7}, {%8,%9}, {%0,%1,%2,%3};"
        : "+f"(c[0]), "+f"(c[1]), "+f"(c[2]), "+f"(c[3])
        : "r"(a0), "r"(a1), "r"(a2), "r"(a3), "r"(b0), "r"(b1));
}

// ============================================================
// Kernel 1: fused degree + exact A copy + tf32-rounded A (g_At).
// One block per row; single streaming pass over A.
// ============================================================
__global__ __launch_bounds__(256) void k_deg_cvt(const float* __restrict__ A,
                                                 float* __restrict__ a_copy,
                                                 int do_copy) {
    const int row = blockIdx.x;
    const float4* __restrict__ Ar = reinterpret_cast<const float4*>(A + (size_t)row * NROW);
    float4* __restrict__ Or = reinterpret_cast<float4*>(a_copy + (size_t)row * NROW);
    float4* __restrict__ Tr = reinterpret_cast<float4*>(g_At + (size_t)row * NROW);

    float cnt = 0.f;
#pragma unroll 4
    for (int c = threadIdx.x; c < NROW / 4; c += 256) {
        float4 v = Ar[c];
        if (do_copy) Or[c] = v;
        float4 t;
        t.x = __uint_as_float(f2tf(v.x));
        t.y = __uint_as_float(f2tf(v.y));
        t.z = __uint_as_float(f2tf(v.z));
        t.w = __uint_as_float(f2tf(v.w));
        Tr[c] = t;
        cnt += (v.x - 1e-15f > 0.f) ? 1.f : 0.f;
        cnt += (v.y - 1e-15f > 0.f) ? 1.f : 0.f;
        cnt += (v.z - 1e-15f > 0.f) ? 1.f : 0.f;
        cnt += (v.w - 1e-15f > 0.f) ? 1.f : 0.f;
    }
#pragma unroll
    for (int o = 16; o; o >>= 1) cnt += __shfl_down_sync(0xffffffffu, cnt, o);

    __shared__ float wsum[8];
    const int warp = threadIdx.x >> 5, lane = threadIdx.x & 31;
    if (lane == 0) wsum[warp] = cnt;
    __syncthreads();
    if (threadIdx.x == 0) {
        float s = 1.f;
#pragma unroll
        for (int i = 0; i < 8; i++) s += wsum[i];
        float r = rsqrtf(s);
        r = r * (1.5f - 0.5f * s * r * r);   // Newton refine
        g_d[row] = r;
    }
}

// ============================================================
// Kernel 2: g_ht[j][i] = tf32( d_i * sum_k W[j,k] * x[i,k] )
// 64x64 tile; coalesced float4 stores along i. grid = (NROW/64, DOUT/64).
// ============================================================
__global__ __launch_bounds__(256) void k_h(const float* __restrict__ x,
                                           const float* __restrict__ W) {
    constexpr int STR = 68;
    __shared__ float wt[32][STR];  // [k][j]
    __shared__ float xt[32][STR];  // [k][i]

    const int tid = threadIdx.x;
    const int tx = tid & 15, ty = tid >> 4;
    const int i0 = blockIdx.x * 64;
    const int j0 = blockIdx.y * 64;

    float acc[4][4];
#pragma unroll
    for (int m = 0; m < 4; m++)
#pragma unroll
        for (int n = 0; n < 4; n++) acc[m][n] = 0.f;

    for (int t = 0; t < DIN / 32; ++t) {
#pragma unroll
        for (int i = 0; i < 2; i++) {
            const int f4 = tid + i * 256;
            const int r = f4 >> 3;
            const int kc = (f4 & 7) * 4;
            float4 wv = *reinterpret_cast<const float4*>(W + (size_t)(j0 + r) * DIN + t * 32 + kc);
            float4 xv = *reinterpret_cast<const float4*>(x + (size_t)(i0 + r) * DIN + t * 32 + kc);
            wt[kc + 0][r] = wv.x; wt[kc + 1][r] = wv.y;
            wt[kc + 2][r] = wv.z; wt[kc + 3][r] = wv.w;
            xt[kc + 0][r] = xv.x; xt[kc + 1][r] = xv.y;
            xt[kc + 2][r] = xv.z; xt[kc + 3][r] = xv.w;
        }
        __syncthreads();
#pragma unroll
        for (int k = 0; k < 32; k++) {
            float4 wv = *reinterpret_cast<const float4*>(&wt[k][ty * 4]);
            float4 xv = *reinterpret_cast<const float4*>(&xt[k][tx * 4]);
            const float wr[4] = {wv.x, wv.y, wv.z, wv.w};
            const float xr[4] = {xv.x, xv.y, xv.z, xv.w};
#pragma unroll
            for (int m = 0; m < 4; m++)
#pragma unroll
                for (int n = 0; n < 4; n++) acc[m][n] += wr[m] * xr[n];
        }
        __syncthreads();
    }

    float dn[4];
#pragma unroll
    for (int e = 0; e < 4; e++) dn[e] = g_d[i0 + tx * 4 + e];
#pragma unroll
    for (int m = 0; m < 4; m++) {
        float4 v;
        v.x = __uint_as_float(f2tf(dn[0] * acc[m][0]));
        v.y = __uint_as_float(f2tf(dn[1] * acc[m][1]));
        v.z = __uint_as_float(f2tf(dn[2] * acc[m][2]));
        v.w = __uint_as_float(f2tf(dn[3] * acc[m][3]));
        *reinterpret_cast<float4*>(&g_ht[(size_t)(j0 + ty * 4 + m) * NROW + i0 + tx * 4]) = v;
    }
}

// ============================================================
// Kernel 3: out = relu(diag(d) * (A @ h' + h')) — cp.async multistage
// mma.sync tf32 GEMM. BM=128, BN=128, BK=32, 4-stage smem ring
// (A 16KB + B 16KB per stage, SW128-swizzled), 256 threads = 8 warps
// as 4(m) x 2(n); warp tile 32x64 = 2 mt x 8 nt of m16n8k8.
// Operands pre-converted (g_At / g_ht) -> hot loop has no cvt, no staging.
// ============================================================
constexpr int KC = 32;
constexpr int NST = NROW / KC;          // 256
constexpr int RING = 4;
constexpr int STG = 32768;              // bytes per stage (A 16K + B 16K)
constexpr int DYN_SMEM = RING * STG;    // 128 KB

__global__ __launch_bounds__(256, 1) void k_main(float* __restrict__ out) {
    extern __shared__ __align__(1024) char dyn[];
    const uint32_t sbase = smem_u32(dyn);

    const int tid = threadIdx.x;
    const int warp = tid >> 5, lane = tid & 31;
    const int wm = warp >> 1, wn = warp & 1;
    const int g = lane >> 2, tg = lane & 3;
    const int row0 = blockIdx.y * 128;
    const int col0 = blockIdx.x * 128;

    // loader: per stage, each thread issues 4 A-chunks + 4 B-chunks (16B each)
    const int lr = tid >> 3;            // base row 0..31 (+32*j)
    const int lc4 = tid & 7;            // 16B column 0..7

    float acc[2][8][4];
#pragma unroll
    for (int mt = 0; mt < 2; mt++)
#pragma unroll
        for (int nt = 0; nt < 8; nt++)
#pragma unroll
            for (int i = 0; i < 4; i++) acc[mt][nt][i] = 0.f;

#define LOAD_STAGE(st) do { \
    const int _s = (st) & (RING - 1); \
    const uint32_t _ab = sbase + _s * STG; \
    const size_t _k0 = (size_t)(st) * KC; \
    _Pragma("unroll") \
    for (int _j = 0; _j < 4; _j++) { \
        const int _r = lr + 32 * _j; \
        const uint32_t _off = SWZ((uint32_t)_r * 128u + (uint32_t)lc4 * 16u); \
        const float* _sa = g_At + (size_t)(row0 + _r) * NROW + _k0 + lc4 * 4; \
        asm volatile("cp.async.cg.shared.global [%0], [%1], 16;" \
                     :: "r"(_ab + _off), "l"(_sa) : "memory"); \
        const float* _sb = g_ht + (size_t)(col0 + _r) * NROW + _k0 + lc4 * 4; \
        asm volatile("cp.async.cg.shared.global [%0], [%1], 16;" \
                     :: "r"(_ab + 16384u + _off), "l"(_sb) : "memory"); \
    } \
    asm volatile("cp.async.commit_group;" ::: "memory"); \
} while (0)

    // prologue: 3 stages in flight
    LOAD_STAGE(0);
    LOAD_STAGE(1);
    LOAD_STAGE(2);

    for (int t = 0; t < NST; ++t) {
        asm volatile("cp.async.wait_group 2;" ::: "memory");
        __syncthreads();

        const char* Ab = dyn + (t & (RING - 1)) * STG;
        const char* Bb = Ab + 16384;

#pragma unroll
        for (int ks = 0; ks < 4; ++ks) {
            const int kk = ks * 8 + tg;
            uint32_t af[2][4];
#pragma unroll
            for (int mt = 0; mt < 2; ++mt) {
                const int r = wm * 32 + mt * 16 + g;
                af[mt][0] = *reinterpret_cast<const uint32_t*>(Ab + SWZ((uint32_t)r * 128u + kk * 4u));
                af[mt][1] = *reinterpret_cast<const uint32_t*>(Ab + SWZ((uint32_t)(r + 8) * 128u + kk * 4u));
                af[mt][2] = *reinterpret_cast<const uint32_t*>(Ab + SWZ((uint32_t)r * 128u + (kk + 4) * 4u));
                af[mt][3] = *reinterpret_cast<const uint32_t*>(Ab + SWZ((uint32_t)(r + 8) * 128u + (kk + 4) * 4u));
            }
#pragma unroll
            for (int nt = 0; nt < 8; ++nt) {
                const int c = wn * 64 + nt * 8 + g;
                const uint32_t bf0 = *reinterpret_cast<const uint32_t*>(Bb + SWZ((uint32_t)c * 128u + kk * 4u));
                const uint32_t bf1 = *reinterpret_cast<const uint32_t*>(Bb + SWZ((uint32_t)c * 128u + (kk + 4) * 4u));
                mma_tf32(acc[0][nt], af[0][0], af[0][1], af[0][2], af[0][3], bf0, bf1);
                mma_tf32(acc[1][nt], af[1][0], af[1][1], af[1][2], af[1][3], bf0, bf1);
            }
        }

        __syncthreads();               // all warps done with stage t-? buffers before refill
        if (t + 3 < NST) LOAD_STAGE(t + 3);
    }
#undef LOAD_STAGE

    // epilogue: out = relu(d_i * (acc + h'_i))   (h' term from g_ht, coalesced in i)
#pragma unroll
    for (int mt = 0; mt < 2; ++mt) {
        const int r_lo = row0 + wm * 32 + mt * 16 + g;
        const int r_hi = r_lo + 8;
        const float dlo = g_d[r_lo];
        const float dhi = g_d[r_hi];
#pragma unroll
        for (int nt = 0; nt < 8; ++nt) {
            const int c = col0 + wn * 64 + nt * 8 + 2 * tg;
            const float h00 = g_ht[(size_t)(c + 0) * NROW + r_lo];
            const float h01 = g_ht[(size_t)(c + 1) * NROW + r_lo];
            const float h10 = g_ht[(size_t)(c + 0) * NROW + r_hi];
            const float h11 = g_ht[(size_t)(c + 1) * NROW + r_hi];
            float2 vlo, vhi;
            vlo.x = fmaxf(dlo * (acc[mt][nt][0] + h00), 0.f);
            vlo.y = fmaxf(dlo * (acc[mt][nt][1] + h01), 0.f);
            vhi.x = fmaxf(dhi * (acc[mt][nt][2] + h10), 0.f);
            vhi.y = fmaxf(dhi * (acc[mt][nt][3] + h11), 0.f);
            *reinterpret_cast<float2*>(out + (size_t)r_lo * DOUT + c) = vlo;
            *reinterpret_cast<float2*>(out + (size_t)r_hi * DOUT + c) = vhi;
        }
    }
}

// ============================================================
// Launch
// ============================================================
extern "C" void kernel_launch(void* const* d_in, const int* in_sizes, int n_in,
                              void* d_out, int out_size) {
    const float* x = (const float*)d_in[0];  // [NROW, DIN]
    const float* A = (const float*)d_in[1];  // [NROW, NROW]
    const float* W = (const float*)d_in[2];  // [DOUT, DIN]
    float* out = (float*)d_out;

    const long long out_elems = (long long)NROW * DOUT;
    const long long a_elems = (long long)NROW * NROW;
    const int do_copy = ((long long)out_size >= out_elems + a_elems) ? 1 : 0;
    float* a_copy = do_copy ? (out + out_elems) : (float*)g_At;  // dummy target if absent

    cudaFuncSetAttribute(k_main, cudaFuncAttributeMaxDynamicSharedMemorySize, DYN_SMEM);

    // 1) degrees + exact A copy + tf32-rounded g_At (one pass over A)
    k_deg_cvt<<<NROW, 256>>>(A, a_copy, do_copy);
    // 2) g_ht = tf32( (diag(d) * x @ W^T)^T )
    k_h<<<dim3(NROW / 64, DOUT / 64), 256>>>(x, W);
    // 3) cp.async multistage tf32 GEMM + fused epilogue
    k_main<<<dim3(DOUT / 128, NROW / 128), 256, DYN_SMEM>>>(out);
}